// round 7
// baseline (speedup 1.0000x reference)
#include <cuda_runtime.h>
#include <cuda_bf16.h>
#include <math.h>
#include <stdint.h>

#define Bc 4
#define Lc 2048
#define Dc 512
#define Hc 8
#define HDc 64
#define BL (Bc*Lc)

// ---------------- scratch (device globals; no allocation allowed) ----------
__device__ __nv_bfloat16 g_Qh[Bc*Hc*Lc*HDc];
__device__ __nv_bfloat16 g_Ql[Bc*Hc*Lc*HDc];
__device__ __nv_bfloat16 g_Kh[Bc*Hc*Lc*HDc];
__device__ __nv_bfloat16 g_Kl[Bc*Hc*Lc*HDc];
__device__ __nv_bfloat16 g_Vh[Bc*Hc*Lc*HDc];
__device__ __nv_bfloat16 g_Vl[Bc*Hc*Lc*HDc];
__device__ __nv_bfloat16 g_CXh[BL*Dc];
__device__ __nv_bfloat16 g_CXl[BL*Dc];

// ---------------- helpers ---------------------------------------------------
__device__ __forceinline__ uint32_t smem_u32(const void* p) {
    uint32_t a;
    asm("{ .reg .u64 t; cvta.to.shared.u64 t, %1; cvt.u32.u64 %0, t; }"
        : "=r"(a) : "l"(p));
    return a;
}
__device__ __forceinline__ void ldsm4(uint32_t* r, uint32_t addr) {
    asm volatile("ldmatrix.sync.aligned.m8n8.x4.shared.b16 {%0,%1,%2,%3}, [%4];"
                 : "=r"(r[0]), "=r"(r[1]), "=r"(r[2]), "=r"(r[3]) : "r"(addr));
}
__device__ __forceinline__ void ldsm4t(uint32_t* r, uint32_t addr) {
    asm volatile("ldmatrix.sync.aligned.m8n8.x4.trans.shared.b16 {%0,%1,%2,%3}, [%4];"
                 : "=r"(r[0]), "=r"(r[1]), "=r"(r[2]), "=r"(r[3]) : "r"(addr));
}
__device__ __forceinline__ void mma16816(float* d, const uint32_t* a,
                                         uint32_t b0, uint32_t b1) {
    asm volatile("mma.sync.aligned.m16n8k16.row.col.f32.bf16.bf16.f32 "
                 "{%0,%1,%2,%3}, {%4,%5,%6,%7}, {%8,%9}, {%0,%1,%2,%3};"
                 : "+f"(d[0]), "+f"(d[1]), "+f"(d[2]), "+f"(d[3])
                 : "r"(a[0]), "r"(a[1]), "r"(a[2]), "r"(a[3]), "r"(b0), "r"(b1));
}
__device__ __forceinline__ uint32_t packbf2(float lo, float hi) {
    __nv_bfloat162 v = __floats2bfloat162_rn(lo, hi);
    return *(uint32_t*)&v;
}
__device__ __forceinline__ void cpasync16(uint32_t s, const void* g) {
    asm volatile("cp.async.cg.shared.global [%0], [%1], 16;" :: "r"(s), "l"(g) : "memory");
}
__device__ __forceinline__ void cp_commit() {
    asm volatile("cp.async.commit_group;" ::: "memory");
}
__device__ __forceinline__ void cp_wait1() {
    asm volatile("cp.async.wait_group 1;" ::: "memory");
}
// convert 8 fp32 (two float4) -> hi uint4 + lo uint4 (bf16x2 lanes)
__device__ __forceinline__ void split8(const float4 v0, const float4 v1,
                                       uint4& hi, uint4& lo) {
    hi.x = packbf2(v0.x, v0.y); hi.y = packbf2(v0.z, v0.w);
    hi.z = packbf2(v1.x, v1.y); hi.w = packbf2(v1.z, v1.w);
    __nv_bfloat162 h;
    h = *(__nv_bfloat162*)&hi.x;
    lo.x = packbf2(v0.x - __bfloat162float(h.x), v0.y - __bfloat162float(h.y));
    h = *(__nv_bfloat162*)&hi.y;
    lo.y = packbf2(v0.z - __bfloat162float(h.x), v0.w - __bfloat162float(h.y));
    h = *(__nv_bfloat162*)&hi.z;
    lo.z = packbf2(v1.x - __bfloat162float(h.x), v1.y - __bfloat162float(h.y));
    h = *(__nv_bfloat162*)&hi.w;
    lo.w = packbf2(v1.z - __bfloat162float(h.x), v1.w - __bfloat162float(h.y));
}

// ---------------------------------------------------------------------------
// Warp-MMA GEMM: out = A @ W^T + bias, fp32 accuracy via 3 hi/lo passes.
// MODE 1 (projection): A fp32 [8192,512], out = bf16 hi/lo in [B,H,L,HD].
// MODE 0 (output proj): A bf16 hi/lo [8192,512], out fp32 [8192,512].
// W always fp32 [512,512]; converted in the loader.
// Block 256 thr (8 warps), tile 128x64, warp 32x32, BK=64.
// ---------------------------------------------------------------------------
#define GSTR 144  // smem row stride bytes (64 bf16 = 128B + 16 pad)
template<int MODE>
__global__ void __launch_bounds__(256) gemm_mma(
    const float* __restrict__ Afp,
    const __nv_bfloat16* __restrict__ Ah, const __nv_bfloat16* __restrict__ Al,
    const float* __restrict__ W,
    const float* __restrict__ bias, float* __restrict__ out,
    __nv_bfloat16* __restrict__ outh, __nv_bfloat16* __restrict__ outl) {
    extern __shared__ char smem[];
    const uint32_t sb = smem_u32(smem);
    const int t = threadIdx.x, lane = t & 31, wid = t >> 5;
    const int wm = wid & 3, wn = wid >> 2;
    const int row0 = blockIdx.y * 128, col0 = blockIdx.x * 64;
    const uint32_t SAH = 0, SAL = 18432, SBH = 36864, SBL = 46080;

    float d[2][4][4];
#pragma unroll
    for (int i = 0; i < 2; i++)
#pragma unroll
        for (int j = 0; j < 4; j++)
#pragma unroll
            for (int e = 0; e < 4; e++) d[i][j][e] = 0.f;

    float4 va[4][2];
    uint4 ra_h[4], ra_l[4];
    float4 vb[2][2];

    auto gload = [&](int kc) {
        const int k0 = kc * 64;
#pragma unroll
        for (int i = 0; i < 4; i++) {
            int idx = i * 256 + t, r = idx >> 3, ce = (idx & 7) * 8;
            if (MODE == 1) {
                const float4* src = (const float4*)(Afp + (size_t)(row0 + r) * 512 + k0 + ce);
                va[i][0] = src[0]; va[i][1] = src[1];
            } else {
                size_t g = (size_t)(row0 + r) * 512 + k0 + ce;
                ra_h[i] = *(const uint4*)(Ah + g);
                ra_l[i] = *(const uint4*)(Al + g);
            }
        }
#pragma unroll
        for (int i = 0; i < 2; i++) {
            int idx = i * 256 + t, r = idx >> 3, ce = (idx & 7) * 8;
            const float4* src = (const float4*)(W + (size_t)(col0 + r) * 512 + k0 + ce);
            vb[i][0] = src[0]; vb[i][1] = src[1];
        }
    };
    auto sstore = [&]() {
#pragma unroll
        for (int i = 0; i < 4; i++) {
            int idx = i * 256 + t, r = idx >> 3, cb = (idx & 7) * 16;
            uint4 hi, lo;
            if (MODE == 1) split8(va[i][0], va[i][1], hi, lo);
            else { hi = ra_h[i]; lo = ra_l[i]; }
            *(uint4*)(smem + SAH + r * GSTR + cb) = hi;
            *(uint4*)(smem + SAL + r * GSTR + cb) = lo;
        }
#pragma unroll
        for (int i = 0; i < 2; i++) {
            int idx = i * 256 + t, r = idx >> 3, cb = (idx & 7) * 16;
            uint4 hi, lo;
            split8(vb[i][0], vb[i][1], hi, lo);
            *(uint4*)(smem + SBH + r * GSTR + cb) = hi;
            *(uint4*)(smem + SBL + r * GSTR + cb) = lo;
        }
    };

    gload(0);
    for (int c = 0; c < 8; c++) {
        __syncthreads();
        sstore();
        __syncthreads();
        if (c < 7) gload(c + 1);
#pragma unroll
        for (int pass = 0; pass < 3; pass++) {
            uint32_t abase = sb + (pass == 1 ? SAL : SAH);
            uint32_t bbase = sb + (pass == 2 ? SBL : SBH);
#pragma unroll
            for (int ks = 0; ks < 4; ks++) {
                uint32_t af[2][4], bf[2][4];
#pragma unroll
                for (int mt = 0; mt < 2; mt++)
                    ldsm4(af[mt], abase + (wm * 32 + mt * 16 + (lane & 15)) * GSTR
                                  + ks * 32 + (lane >> 4) * 16);
#pragma unroll
                for (int bp = 0; bp < 2; bp++)
                    ldsm4(bf[bp], bbase + (wn * 32 + bp * 16 + (lane & 15)) * GSTR
                                  + ks * 32 + (lane >> 4) * 16);
#pragma unroll
                for (int mt = 0; mt < 2; mt++)
#pragma unroll
                    for (int nt = 0; nt < 4; nt++)
                        mma16816(d[mt][nt], af[mt], bf[nt >> 1][nt & 1], bf[nt >> 1][(nt & 1) + 2]);
            }
        }
    }

    // epilogue
#pragma unroll
    for (int mt = 0; mt < 2; mt++) {
        int r1 = row0 + wm * 32 + mt * 16 + (lane >> 2);
#pragma unroll
        for (int nt = 0; nt < 4; nt++) {
            int cc = col0 + wn * 32 + nt * 8 + (lane & 3) * 2;
            float b0 = bias[cc], b1 = bias[cc + 1];
            float v00 = d[mt][nt][0] + b0, v01 = d[mt][nt][1] + b1;
            float v10 = d[mt][nt][2] + b0, v11 = d[mt][nt][3] + b1;
            if (MODE == 0) {
                *(float2*)(out + (size_t)r1 * 512 + cc) = make_float2(v00, v01);
                *(float2*)(out + (size_t)(r1 + 8) * 512 + cc) = make_float2(v10, v11);
            } else {
                int hd = cc - col0;
#pragma unroll
                for (int rr = 0; rr < 2; rr++) {
                    int r = r1 + rr * 8;
                    float va0 = rr ? v10 : v00, va1 = rr ? v11 : v01;
                    int b = r >> 11, l = r & 2047;
                    size_t idx = (((size_t)(b * Hc + blockIdx.x)) * Lc + l) * HDc + hd;
                    __nv_bfloat16 ha = __float2bfloat16(va0), hb = __float2bfloat16(va1);
                    *(__nv_bfloat162*)(outh + idx) = __halves2bfloat162(ha, hb);
                    *(__nv_bfloat162*)(outl + idx) = __halves2bfloat162(
                        __float2bfloat16(va0 - __bfloat162float(ha)),
                        __float2bfloat16(va1 - __bfloat162float(hb)));
                }
            }
        }
    }
}

// ---------------------------------------------------------------------------
// Warp-MMA causal flash attention, cp.async double-buffered K/V.
// Grid (16, H, B), block 256 (8 warps). 128-query tile; warp w owns rows
// w*16..+15. K/V tiles 64-wide, 2 smem stages. Output bf16 hi/lo ctx [B,L,D].
// ---------------------------------------------------------------------------
__global__ void __launch_bounds__(256) flash_mma() {
    extern __shared__ char smem[];
    const uint32_t sb = smem_u32(smem);
    const int t = threadIdx.x, lane = t & 31, w = t >> 5;
    const int qt = 15 - blockIdx.x;  // heavy tiles first
    const int h = blockIdx.y, b = blockIdx.z;
    const size_t base = ((size_t)(b * Hc + h)) * Lc * HDc;
    const uint32_t SQH = 0, SQL = 18432, SST = 36864, STSZ = 36864;
    const uint32_t OKL = 9216, OVH = 18432, OVL = 27648;

    const int njt = 2 * qt + 2;

    // async prefetch of K/V stage
    auto pf = [&](int jt, int st) {
        uint32_t dstb = sb + SST + st * STSZ;
#pragma unroll
        for (int i = 0; i < 2; i++) {
            int idx = i * 256 + t, r = idx >> 3, cb = (idx & 7) * 16, ce = (idx & 7) * 8;
            size_t g = base + (size_t)(jt * 64 + r) * HDc + ce;
            uint32_t d0 = dstb + r * GSTR + cb;
            cpasync16(d0,        g_Kh + g);
            cpasync16(d0 + OKL,  g_Kl + g);
            cpasync16(d0 + OVH,  g_Vh + g);
            cpasync16(d0 + OVL,  g_Vl + g);
        }
    };

    // kick off stage 0 before the Q-tile load (overlap)
    pf(0, 0);
    cp_commit();

    // load Q tile (128 rows x 64 bf16, hi+lo)
#pragma unroll
    for (int i = 0; i < 4; i++) {
        int idx = i * 256 + t, r = idx >> 3, cb = (idx & 7) * 16, ce = (idx & 7) * 8;
        size_t g = base + (size_t)(qt * 128 + r) * HDc + ce;
        *(uint4*)(smem + SQH + r * GSTR + cb) = *(const uint4*)(g_Qh + g);
        *(uint4*)(smem + SQL + r * GSTR + cb) = *(const uint4*)(g_Ql + g);
    }
    __syncthreads();

    uint32_t qfh[4][4], qfl[4][4];
#pragma unroll
    for (int ks = 0; ks < 4; ks++) {
        uint32_t a = (w * 16 + (lane & 15)) * GSTR + ks * 32 + (lane >> 4) * 16;
        ldsm4(qfh[ks], sb + SQH + a);
        ldsm4(qfl[ks], sb + SQL + a);
    }

    float o[8][4];
#pragma unroll
    for (int i = 0; i < 8; i++)
#pragma unroll
        for (int e = 0; e < 4; e++) o[i][e] = 0.f;
    float m0 = -1e30f, m1 = -1e30f, l0 = 0.f, l1 = 0.f;
    const float scale = 0.125f;
    const int qlo = qt * 128 + w * 16;

    for (int jt = 0; jt < njt; jt++) {
        // prefetch next stage while computing this one
        if (jt + 1 < njt) pf(jt + 1, (jt + 1) & 1);
        cp_commit();
        cp_wait1();            // stage jt resident
        __syncthreads();       // visible to all warps; prior compute drained

        const int J0 = jt * 64;
        const uint32_t stb = sb + SST + (jt & 1) * STSZ;

        if (J0 <= qlo + 15) {
            // ---- S = Q K^T (3 passes) ----
            float s[8][4];
#pragma unroll
            for (int i = 0; i < 8; i++)
#pragma unroll
                for (int e = 0; e < 4; e++) s[i][e] = 0.f;
#pragma unroll
            for (int pass = 0; pass < 3; pass++) {
                const uint32_t (*af)[4] = (pass == 1) ? qfl : qfh;
                uint32_t bbase = stb + ((pass == 2) ? OKL : 0);
#pragma unroll
                for (int ks = 0; ks < 4; ks++) {
#pragma unroll
                    for (int bp = 0; bp < 4; bp++) {
                        uint32_t bf[4];
                        ldsm4(bf, bbase + (bp * 16 + (lane & 15)) * GSTR + ks * 32 + (lane >> 4) * 16);
                        mma16816(s[bp * 2],     af[ks], bf[0], bf[2]);
                        mma16816(s[bp * 2 + 1], af[ks], bf[1], bf[3]);
                    }
                }
            }

            // ---- scale + causal mask ----
            if (J0 + 63 > qlo) {
                int q0 = qlo + (lane >> 2);
#pragma unroll
                for (int nt = 0; nt < 8; nt++) {
                    int kc = J0 + nt * 8 + (lane & 3) * 2;
                    s[nt][0] = (kc     <= q0)     ? s[nt][0] * scale : -1e30f;
                    s[nt][1] = (kc + 1 <= q0)     ? s[nt][1] * scale : -1e30f;
                    s[nt][2] = (kc     <= q0 + 8) ? s[nt][2] * scale : -1e30f;
                    s[nt][3] = (kc + 1 <= q0 + 8) ? s[nt][3] * scale : -1e30f;
                }
            } else {
#pragma unroll
                for (int nt = 0; nt < 8; nt++)
#pragma unroll
                    for (int e = 0; e < 4; e++) s[nt][e] *= scale;
            }

            // ---- online softmax ----
            float a0 = -1e30f, a1 = -1e30f;
#pragma unroll
            for (int nt = 0; nt < 8; nt++) {
                a0 = fmaxf(a0, fmaxf(s[nt][0], s[nt][1]));
                a1 = fmaxf(a1, fmaxf(s[nt][2], s[nt][3]));
            }
            a0 = fmaxf(a0, __shfl_xor_sync(0xffffffffu, a0, 1));
            a0 = fmaxf(a0, __shfl_xor_sync(0xffffffffu, a0, 2));
            a1 = fmaxf(a1, __shfl_xor_sync(0xffffffffu, a1, 1));
            a1 = fmaxf(a1, __shfl_xor_sync(0xffffffffu, a1, 2));
            float n0 = fmaxf(m0, a0), n1 = fmaxf(m1, a1);
            float c0 = __expf(m0 - n0), c1 = __expf(m1 - n1);
            m0 = n0; m1 = n1; l0 *= c0; l1 *= c1;
#pragma unroll
            for (int nt = 0; nt < 8; nt++) {
                o[nt][0] *= c0; o[nt][1] *= c0; o[nt][2] *= c1; o[nt][3] *= c1;
            }

            // ---- P = exp(S - m); PV accumulation ----
#pragma unroll
            for (int ks = 0; ks < 4; ks++) {
                float p[8];
                p[0] = __expf(s[2 * ks][0] - n0);     p[1] = __expf(s[2 * ks][1] - n0);
                p[2] = __expf(s[2 * ks][2] - n1);     p[3] = __expf(s[2 * ks][3] - n1);
                p[4] = __expf(s[2 * ks + 1][0] - n0); p[5] = __expf(s[2 * ks + 1][1] - n0);
                p[6] = __expf(s[2 * ks + 1][2] - n1); p[7] = __expf(s[2 * ks + 1][3] - n1);
                l0 += p[0] + p[1] + p[4] + p[5];
                l1 += p[2] + p[3] + p[6] + p[7];
                uint32_t ph[4], pl[4];
#pragma unroll
                for (int j = 0; j < 4; j++) {
                    float e0 = p[j * 2], e1 = p[j * 2 + 1];
                    ph[j] = packbf2(e0, e1);
                    __nv_bfloat162 hv = *(__nv_bfloat162*)&ph[j];
                    pl[j] = packbf2(e0 - __bfloat162float(hv.x), e1 - __bfloat162float(hv.y));
                }
#pragma unroll
                for (int np = 0; np < 4; np++) {
                    uint32_t a = stb + OVH + (ks * 16 + (lane & 15)) * GSTR + np * 32 + (lane >> 4) * 16;
                    uint32_t vh[4], vl[4];
                    ldsm4t(vh, a);
                    ldsm4t(vl, a + (OVL - OVH));
                    mma16816(o[np * 2],     ph, vh[0], vh[1]);
                    mma16816(o[np * 2 + 1], ph, vh[2], vh[3]);
                    mma16816(o[np * 2],     pl, vh[0], vh[1]);
                    mma16816(o[np * 2 + 1], pl, vh[2], vh[3]);
                    mma16816(o[np * 2],     ph, vl[0], vl[1]);
                    mma16816(o[np * 2 + 1], ph, vl[2], vl[3]);
                }
            }
        }
        __syncthreads();  // all warps done with stage jt before it is overwritten
    }

    // ---- finalize: write bf16 hi/lo ctx in [B,L,D] ----
    l0 += __shfl_xor_sync(0xffffffffu, l0, 1);
    l0 += __shfl_xor_sync(0xffffffffu, l0, 2);
    l1 += __shfl_xor_sync(0xffffffffu, l1, 1);
    l1 += __shfl_xor_sync(0xffffffffu, l1, 2);
    float i0 = 1.f / l0, i1 = 1.f / l1;
    int qrow = qt * 128 + w * 16 + (lane >> 2);
    size_t r0 = (size_t)b * Lc + qrow;
#pragma unroll
    for (int nt = 0; nt < 8; nt++) {
        int cc = h * HDc + nt * 8 + (lane & 3) * 2;
#pragma unroll
        for (int rr = 0; rr < 2; rr++) {
            float va0 = (rr ? o[nt][2] * i1 : o[nt][0] * i0);
            float va1 = (rr ? o[nt][3] * i1 : o[nt][1] * i0);
            size_t idx = (r0 + rr * 8) * Dc + cc;
            __nv_bfloat16 ha = __float2bfloat16(va0), hb = __float2bfloat16(va1);
            *(__nv_bfloat162*)(g_CXh + idx) = __halves2bfloat162(ha, hb);
            *(__nv_bfloat162*)(g_CXl + idx) = __halves2bfloat162(
                __float2bfloat16(va0 - __bfloat162float(ha)),
                __float2bfloat16(va1 - __bfloat162float(hb)));
        }
    }
}

// ---------------------------------------------------------------------------
extern "C" void kernel_launch(void* const* d_in, const int* in_sizes, int n_in,
                              void* d_out, int out_size) {
    const float* q  = (const float*)d_in[0];
    const float* k  = (const float*)d_in[1];
    const float* v  = (const float*)d_in[2];
    const float* Wq = (const float*)d_in[4];
    const float* bq = (const float*)d_in[5];
    const float* Wk = (const float*)d_in[6];
    const float* bk = (const float*)d_in[7];
    const float* Wv = (const float*)d_in[8];
    const float* bv = (const float*)d_in[9];
    const float* Wo = (const float*)d_in[10];
    const float* bo = (const float*)d_in[11];
    float* out = (float*)d_out;

    __nv_bfloat16 *Qh, *Ql, *Kh, *Kl, *Vh, *Vl, *CXh, *CXl;
    cudaGetSymbolAddress((void**)&Qh, g_Qh);
    cudaGetSymbolAddress((void**)&Ql, g_Ql);
    cudaGetSymbolAddress((void**)&Kh, g_Kh);
    cudaGetSymbolAddress((void**)&Kl, g_Kl);
    cudaGetSymbolAddress((void**)&Vh, g_Vh);
    cudaGetSymbolAddress((void**)&Vl, g_Vl);
    cudaGetSymbolAddress((void**)&CXh, g_CXh);
    cudaGetSymbolAddress((void**)&CXl, g_CXl);

    const int gsmem = 55296;
    const int fsmem = 36864 + 2 * 36864;  // 110592
    cudaFuncSetAttribute(gemm_mma<0>, cudaFuncAttributeMaxDynamicSharedMemorySize, gsmem);
    cudaFuncSetAttribute(gemm_mma<1>, cudaFuncAttributeMaxDynamicSharedMemorySize, gsmem);
    cudaFuncSetAttribute(flash_mma, cudaFuncAttributeMaxDynamicSharedMemorySize, fsmem);

    dim3 grd_gemm(Dc / 64, BL / 128);  // 8 x 64

    gemm_mma<1><<<grd_gemm, 256, gsmem>>>(q, nullptr, nullptr, Wq, bq, nullptr, Qh, Ql);
    gemm_mma<1><<<grd_gemm, 256, gsmem>>>(k, nullptr, nullptr, Wk, bk, nullptr, Kh, Kl);
    gemm_mma<1><<<grd_gemm, 256, gsmem>>>(v, nullptr, nullptr, Wv, bv, nullptr, Vh, Vl);

    dim3 grd_fa(Lc / 128, Hc, Bc);     // 16 x 8 x 4
    flash_mma<<<grd_fa, 256, fsmem>>>();

    gemm_mma<0><<<grd_gemm, 256, gsmem>>>(nullptr, CXh, CXl, Wo, bo, out, nullptr, nullptr);
}